// round 6
// baseline (speedup 1.0000x reference)
#include <cuda_runtime.h>
#include <cuda_bf16.h>
#include <cuda_fp16.h>
#include <math.h>

// Rigid-warp + trilinear resample of a 256^3 fp32 volume.
// Strategy: pass 1 builds a duplicated z-pair fp16 volume
//   g_pairs[x][y][z] = half2( X[x][y][z], X[x][y][min(z+1,255)] )
// so pass 2 fetches BOTH z-taps of each of the 4 (x,y) rows with a single
// 4-byte load at arbitrary z — no alignment fixup, no selects, no shuffles.
// All interpolation arithmetic stays fp32; only tap storage is fp16.

#define DIMD 256
#define DIMH 256
#define DIMW 256
#define NVOX (DIMD * DIMH * DIMW)

__device__ float g_T[12];
__device__ unsigned int g_pairs[NVOX];   // 64 MB static scratch (half2 per voxel)

static __device__ __forceinline__ unsigned int h2_to_u32(__half2 h) {
    return *reinterpret_cast<unsigned int*>(&h);
}

__device__ __forceinline__ void matmul3(const float a[9], const float b[9], float c[9]) {
    #pragma unroll
    for (int i = 0; i < 3; i++)
        #pragma unroll
        for (int j = 0; j < 3; j++)
            c[i * 3 + j] = a[i * 3 + 0] * b[0 * 3 + j]
                         + a[i * 3 + 1] * b[1 * 3 + j]
                         + a[i * 3 + 2] * b[2 * 3 + j];
}

__device__ __forceinline__ void matmul4(const float a[16], const float b[16], float c[16]) {
    #pragma unroll
    for (int i = 0; i < 4; i++)
        #pragma unroll
        for (int j = 0; j < 4; j++)
            c[i * 4 + j] = a[i * 4 + 0] * b[0 * 4 + j]
                         + a[i * 4 + 1] * b[1 * 4 + j]
                         + a[i * 4 + 2] * b[2 * 4 + j]
                         + a[i * 4 + 3] * b[3 * 4 + j];
}

__device__ void inv4(const float m[16], float invOut[16]) {
    float inv[16];
    inv[0]  =  m[5]*m[10]*m[15] - m[5]*m[11]*m[14] - m[9]*m[6]*m[15] +
               m[9]*m[7]*m[14]  + m[13]*m[6]*m[11] - m[13]*m[7]*m[10];
    inv[4]  = -m[4]*m[10]*m[15] + m[4]*m[11]*m[14] + m[8]*m[6]*m[15] -
               m[8]*m[7]*m[14]  - m[12]*m[6]*m[11] + m[12]*m[7]*m[10];
    inv[8]  =  m[4]*m[9]*m[15]  - m[4]*m[11]*m[13] - m[8]*m[5]*m[15] +
               m[8]*m[7]*m[13]  + m[12]*m[5]*m[11] - m[12]*m[7]*m[9];
    inv[12] = -m[4]*m[9]*m[14]  + m[4]*m[10]*m[13] + m[8]*m[5]*m[14] -
               m[8]*m[6]*m[13]  - m[12]*m[5]*m[10] + m[12]*m[6]*m[9];
    inv[1]  = -m[1]*m[10]*m[15] + m[1]*m[11]*m[14] + m[9]*m[2]*m[15] -
               m[9]*m[3]*m[14]  - m[13]*m[2]*m[11] + m[13]*m[3]*m[10];
    inv[5]  =  m[0]*m[10]*m[15] - m[0]*m[11]*m[14] - m[8]*m[2]*m[15] +
               m[8]*m[3]*m[14]  + m[12]*m[2]*m[11] - m[12]*m[3]*m[10];
    inv[9]  = -m[0]*m[9]*m[15]  + m[0]*m[11]*m[13] + m[8]*m[1]*m[15] -
               m[8]*m[3]*m[13]  - m[12]*m[1]*m[11] + m[12]*m[3]*m[9];
    inv[13] =  m[0]*m[9]*m[14]  - m[0]*m[10]*m[13] - m[8]*m[1]*m[14] +
               m[8]*m[2]*m[13]  + m[12]*m[1]*m[10] - m[12]*m[2]*m[9];
    inv[2]  =  m[1]*m[6]*m[15]  - m[1]*m[7]*m[14]  - m[5]*m[2]*m[15] +
               m[5]*m[3]*m[14]  + m[13]*m[2]*m[7]  - m[13]*m[3]*m[6];
    inv[6]  = -m[0]*m[6]*m[15]  + m[0]*m[7]*m[14]  + m[4]*m[2]*m[15] -
               m[4]*m[3]*m[14]  - m[12]*m[2]*m[7]  + m[12]*m[3]*m[6];
    inv[10] =  m[0]*m[5]*m[15]  - m[0]*m[7]*m[13]  - m[4]*m[1]*m[15] +
               m[4]*m[3]*m[13]  + m[12]*m[1]*m[7]  - m[12]*m[3]*m[5];
    inv[14] = -m[0]*m[5]*m[14]  + m[0]*m[6]*m[13]  + m[4]*m[1]*m[14] -
               m[4]*m[2]*m[13]  - m[12]*m[1]*m[6]  + m[12]*m[2]*m[5];
    inv[3]  = -m[1]*m[6]*m[11]  + m[1]*m[7]*m[10]  + m[5]*m[2]*m[11] -
               m[5]*m[3]*m[10]  - m[9]*m[2]*m[7]   + m[9]*m[3]*m[6];
    inv[7]  =  m[0]*m[6]*m[11]  - m[0]*m[7]*m[10]  - m[4]*m[2]*m[11] +
               m[4]*m[3]*m[10]  + m[8]*m[2]*m[7]   - m[8]*m[3]*m[6];
    inv[11] = -m[0]*m[5]*m[11]  + m[0]*m[7]*m[9]   + m[4]*m[1]*m[11] -
               m[4]*m[3]*m[9]   - m[8]*m[1]*m[7]   + m[8]*m[3]*m[5];
    inv[15] =  m[0]*m[5]*m[10]  - m[0]*m[6]*m[9]   - m[4]*m[1]*m[10] +
               m[4]*m[2]*m[9]   + m[8]*m[1]*m[6]   - m[8]*m[2]*m[5];

    float det = m[0]*inv[0] + m[1]*inv[4] + m[2]*inv[8] + m[3]*inv[12];
    det = 1.0f / det;
    #pragma unroll
    for (int i = 0; i < 16; i++) invOut[i] = inv[i] * det;
}

__global__ void compute_transform_kernel(const float* __restrict__ rot,
                                         const float* __restrict__ tra,
                                         const float* __restrict__ ref_v2r,
                                         const float* __restrict__ flo_v2r) {
    float cx = cosf(rot[0]), cy = cosf(rot[1]), cz = cosf(rot[2]);
    float sx = sinf(rot[0]), sy = sinf(rot[1]), sz = sinf(rot[2]);

    float Rx[9] = {1, 0, 0,  0, cx, -sx,  0, sx, cx};
    float Ry[9] = {cy, 0, sy,  0, 1, 0,  -sy, 0, cy};
    float Rz[9] = {cz, -sz, 0,  sz, cz, 0,  0, 0, 1};
    float RxRy[9], R[9];
    matmul3(Rx, Ry, RxRy);
    matmul3(RxRy, Rz, R);

    float Trig[16] = {
        R[0], R[1], R[2], tra[0],
        R[3], R[4], R[5], tra[1],
        R[6], R[7], R[8], tra[2],
        0.f,  0.f,  0.f,  1.f
    };

    float ref[16], flo[16];
    #pragma unroll
    for (int i = 0; i < 16; i++) { ref[i] = ref_v2r[i]; flo[i] = flo_v2r[i]; }

    float flo_inv[16], A[16], T[16];
    inv4(flo, flo_inv);
    matmul4(Trig, ref, A);
    matmul4(flo_inv, A, T);

    #pragma unroll
    for (int i = 0; i < 12; i++) g_T[i] = T[i];
}

// Pass 1: build duplicated z-pair fp16 volume. Each thread handles 4
// consecutive z of one row: one float4 read + (maybe) one scalar read,
// one uint4 write. Pairing never crosses a row (z=255 duplicates).
__global__ void __launch_bounds__(256)
build_pairs_kernel(const float* __restrict__ X) {
    const int t = blockIdx.x * 256 + threadIdx.x;     // 4-voxel group id
    const int base = t << 2;
    const int kb = base & (DIMW - 1);                 // 0..252 step 4

    const float4 v = __ldg((const float4*)(X + base));
    const float nxt = (kb < DIMW - 4) ? __ldg(X + base + 4) : v.w;

    uint4 o;
    o.x = h2_to_u32(__floats2half2_rn(v.x, v.y));
    o.y = h2_to_u32(__floats2half2_rn(v.y, v.z));
    o.z = h2_to_u32(__floats2half2_rn(v.z, v.w));
    o.w = h2_to_u32(__floats2half2_rn(v.w, nxt));
    *((uint4*)(g_pairs + base)) = o;
}

// Pass 2: warp + trilinear using pair loads (4 loads per output).
__global__ void __launch_bounds__(256)
warp_trilinear_pair_kernel(float* __restrict__ out) {
    const int k = threadIdx.x;            // W (stride-1)
    const int j = blockIdx.x & (DIMH - 1);
    const int i = blockIdx.x >> 8;        // D

    const float T00 = g_T[0], T01 = g_T[1], T02 = g_T[2],  T03 = g_T[3];
    const float T10 = g_T[4], T11 = g_T[5], T12 = g_T[6],  T13 = g_T[7];
    const float T20 = g_T[8], T21 = g_T[9], T22 = g_T[10], T23 = g_T[11];

    const float fi = (float)i, fj = (float)j, fk = (float)k;
    const float di = fmaf(T00, fi, fmaf(T01, fj, fmaf(T02, fk, T03)));
    const float dj = fmaf(T10, fi, fmaf(T11, fj, fmaf(T12, fk, T13)));
    const float dk = fmaf(T20, fi, fmaf(T21, fj, fmaf(T22, fk, T23)));

    const int idx = (i << 16) | (j << 8) | k;
    const float MX = 255.f;

    // strictly-interior mask (matches reference: >0 and <= dim-1)
    const bool ok = (di > 0.f) & (dj > 0.f) & (dk > 0.f) &
                    (di <= MX) & (dj <= MX) & (dk <= MX);
    if (!ok) { out[idx] = 0.f; return; }

    const float fx = floorf(di), fy = floorf(dj), fz = floorf(dk);
    const float wcx = di - fx, wcy = dj - fy, wcz = dk - fz;
    const float wfx = 1.f - wcx, wfy = 1.f - wcy, wfz = 1.f - wcz;

    // ok => coords in (0,255], so floor in [0,255]
    const int x0 = (int)fx, y0 = (int)fy, z0 = (int)fz;
    const int x1 = min(x0 + 1, DIMD - 1);
    const int y1 = min(y0 + 1, DIMH - 1);

    const int bx0 = x0 << 16, bx1 = x1 << 16;
    const int by0 = y0 << 8,  by1 = y1 << 8;

    // one 4-byte load per (x,y) row: (tap_z0, tap_z1) as half2
    unsigned int u00 = __ldg(g_pairs + (bx0 | by0) + z0);
    unsigned int u01 = __ldg(g_pairs + (bx0 | by1) + z0);
    unsigned int u10 = __ldg(g_pairs + (bx1 | by0) + z0);
    unsigned int u11 = __ldg(g_pairs + (bx1 | by1) + z0);

    const float2 f00 = __half22float2(*reinterpret_cast<const __half2*>(&u00));
    const float2 f01 = __half22float2(*reinterpret_cast<const __half2*>(&u01));
    const float2 f10 = __half22float2(*reinterpret_cast<const __half2*>(&u10));
    const float2 f11 = __half22float2(*reinterpret_cast<const __half2*>(&u11));

    const float c00 = fmaf(f00.x, wfz, f00.y * wcz);
    const float c01 = fmaf(f01.x, wfz, f01.y * wcz);
    const float c10 = fmaf(f10.x, wfz, f10.y * wcz);
    const float c11 = fmaf(f11.x, wfz, f11.y * wcz);

    const float c0 = fmaf(c00, wfy, c01 * wcy);
    const float c1 = fmaf(c10, wfy, c11 * wcy);

    out[idx] = fmaf(c0, wfx, c1 * wcx);
}

extern "C" void kernel_launch(void* const* d_in, const int* in_sizes, int n_in,
                              void* d_out, int out_size) {
    const float* image = (const float*)d_in[0];
    const float* rot   = (const float*)d_in[1];
    const float* tra   = (const float*)d_in[2];
    const float* refm  = (const float*)d_in[3];
    const float* flom  = (const float*)d_in[4];
    float* out = (float*)d_out;

    compute_transform_kernel<<<1, 1>>>(rot, tra, refm, flom);
    build_pairs_kernel<<<NVOX / 4 / 256, 256>>>(image);
    warp_trilinear_pair_kernel<<<DIMD * DIMH, DIMW>>>(out);
}